// round 4
// baseline (speedup 1.0000x reference)
#include <cuda_runtime.h>
#include <math.h>

#define B_    64
#define P_    196
#define ENC_  512
#define EMB_  256
#define ATT_  256
#define DEC_  256
#define V_    10000
#define T_    44
#define NG_   1024           // 4*DEC
#define KX2_  768            // ENC + DEC (emb part hoisted out of loop)
#define SPLITK_ 12           // gates GEMM K chunks of 64

// ---------------- device scratch (static: no allocation allowed) ----------------
__device__ float g_att1[B_ * P_ * ATT_];        // encoder attention keys
__device__ float g_WdaT[ATT_ * DEC_];           // W_dec_att transposed [k][j]
__device__ float g_Wcat2[NG_ * KX2_];           // [W_ih[:, :512] | W_hh] row-major [j][k]
__device__ float g_Wemb[NG_ * EMB_];            // W_ih[:, 512:768]
__device__ float g_embx[T_ * B_ * EMB_];        // gathered embeddings, all steps
__device__ float g_gemb[T_ * B_ * NG_];         // precomputed emb gate contributions
__device__ float g_h0[B_ * DEC_];
__device__ float g_c[B_ * DEC_];
__device__ float g_x[B_ * KX2_];                // per-step LSTM input [ctx | h]
__device__ float g_gpart[SPLITK_ * B_ * NG_];   // split-K gate partials
__device__ float g_hall[T_ * B_ * DEC_];        // all hidden states for batched logits

__device__ __forceinline__ float sigm(float x) { return 1.0f / (1.0f + expf(-x)); }

// ---------------- one-time weight prep (transpose / concat / gather) ----------------
__global__ void k_prep(const float* __restrict__ W_ih, const float* __restrict__ W_hh,
                       const float* __restrict__ W_dec_att,
                       const float* __restrict__ embedding, const int* __restrict__ caption) {
    int idx = blockIdx.x * blockDim.x + threadIdx.x;
    if (idx < NG_ * KX2_) {
        int j = idx / KX2_, k = idx % KX2_;
        g_Wcat2[idx] = (k < 512) ? W_ih[j * 768 + k] : W_hh[j * 256 + (k - 512)];
    }
    int i2 = idx - NG_ * KX2_;
    if (i2 >= 0 && i2 < ATT_ * DEC_) {
        int k = i2 >> 8, j = i2 & 255;
        g_WdaT[i2] = W_dec_att[j * 256 + k];
    }
    int i3 = i2 - ATT_ * DEC_;
    if (i3 >= 0 && i3 < NG_ * EMB_) {
        int j = i3 >> 8, k = i3 & 255;
        g_Wemb[i3] = W_ih[j * 768 + 512 + k];
    }
    int i4 = i3 - NG_ * EMB_;
    if (i4 >= 0 && i4 < T_ * B_ * EMB_) {
        int m = i4 >> 8, k = i4 & 255;
        int b = m & (B_ - 1), t = m >> 6;
        g_embx[i4] = embedding[(size_t)caption[b * T_ + t] * EMB_ + k];
    }
}

// ---------------- init h0/c0 from mean-pooled encoder ----------------
__global__ void k_init(const float* __restrict__ enc,
                       const float* __restrict__ W_init_h, const float* __restrict__ b_init_h,
                       const float* __restrict__ W_init_c, const float* __restrict__ b_init_c) {
    int b = blockIdx.x, tid = threadIdx.x;
    __shared__ float avg[ENC_];
    #pragma unroll
    for (int e0 = 0; e0 < 2; e0++) {
        int e = tid + e0 * 256;
        float s = 0.f;
        for (int p = 0; p < P_; p++) s += enc[((size_t)(b * P_ + p)) * ENC_ + e];
        avg[e] = s * (1.0f / (float)P_);
    }
    __syncthreads();
    float h = b_init_h[tid], c = b_init_c[tid];
    const float* wh = W_init_h + (size_t)tid * ENC_;
    const float* wc = W_init_c + (size_t)tid * ENC_;
    #pragma unroll 8
    for (int k = 0; k < ENC_; k++) { h += avg[k] * wh[k]; c += avg[k] * wc[k]; }
    g_h0[b * DEC_ + tid] = h;
    g_c[b * DEC_ + tid] = c;
}

// ---------------- 128x128 tiled SGEMM, 8x8/thread, double-buffered smem ----------------
// C[m][n] = sum_k A[m][k]*Bm[n][k] (+bias)
// PERM=1: row m encodes (t*B + b); store to C[(b*T + t)*V + n] (logits epilogue)
// Requires M % 128 == 0, K % 32 == 0. N guarded.
template<int PERM>
__global__ __launch_bounds__(256) void sgemm128(
        const float* __restrict__ A, const float* __restrict__ Bm,
        const float* __restrict__ bias, float* __restrict__ C,
        int M, int N, int K) {
    __shared__ float As[2][16][132];
    __shared__ float Bs[2][16][132];
    int tid = threadIdx.x;
    int m0 = blockIdx.x * 128, n0 = blockIdx.y * 128;
    int tx = tid & 15, ty = tid >> 4;
    int lrow = tid >> 2;           // 0..63
    int lkc  = (tid & 3) * 4;      // 0,4,8,12

    const float* Ap0 = A + (size_t)(m0 + lrow) * K + lkc;
    const float* Ap1 = A + (size_t)(m0 + lrow + 64) * K + lkc;
    bool bok0 = (n0 + lrow) < N, bok1 = (n0 + lrow + 64) < N;
    const float* Bp0 = Bm + (size_t)(bok0 ? n0 + lrow : 0) * K + lkc;
    const float* Bp1 = Bm + (size_t)(bok1 ? n0 + lrow + 64 : 0) * K + lkc;
    const float4 z4 = make_float4(0.f, 0.f, 0.f, 0.f);

    // initial tile -> buffer 0
    {
        float4 a0 = *(const float4*)Ap0;
        float4 a1 = *(const float4*)Ap1;
        float4 b0 = bok0 ? *(const float4*)Bp0 : z4;
        float4 b1 = bok1 ? *(const float4*)Bp1 : z4;
        As[0][lkc+0][lrow] = a0.x; As[0][lkc+1][lrow] = a0.y; As[0][lkc+2][lrow] = a0.z; As[0][lkc+3][lrow] = a0.w;
        As[0][lkc+0][lrow+64] = a1.x; As[0][lkc+1][lrow+64] = a1.y; As[0][lkc+2][lrow+64] = a1.z; As[0][lkc+3][lrow+64] = a1.w;
        Bs[0][lkc+0][lrow] = b0.x; Bs[0][lkc+1][lrow] = b0.y; Bs[0][lkc+2][lrow] = b0.z; Bs[0][lkc+3][lrow] = b0.w;
        Bs[0][lkc+0][lrow+64] = b1.x; Bs[0][lkc+1][lrow+64] = b1.y; Bs[0][lkc+2][lrow+64] = b1.z; Bs[0][lkc+3][lrow+64] = b1.w;
    }
    __syncthreads();

    float acc[8][8] = {};
    int buf = 0;
    for (int k0 = 16; k0 < K; k0 += 16) {
        // prefetch next tile into registers (latency hidden by compute below)
        float4 a0 = *(const float4*)(Ap0 + k0);
        float4 a1 = *(const float4*)(Ap1 + k0);
        float4 b0 = bok0 ? *(const float4*)(Bp0 + k0) : z4;
        float4 b1 = bok1 ? *(const float4*)(Bp1 + k0) : z4;
        // compute on current buffer
        #pragma unroll
        for (int kk = 0; kk < 16; kk++) {
            float a[8], b[8];
            *(float4*)&a[0] = *(const float4*)&As[buf][kk][ty * 4];
            *(float4*)&a[4] = *(const float4*)&As[buf][kk][64 + ty * 4];
            *(float4*)&b[0] = *(const float4*)&Bs[buf][kk][tx * 4];
            *(float4*)&b[4] = *(const float4*)&Bs[buf][kk][64 + tx * 4];
            #pragma unroll
            for (int i = 0; i < 8; i++)
                #pragma unroll
                for (int j = 0; j < 8; j++) acc[i][j] += a[i] * b[j];
        }
        // store prefetched into the other buffer
        int nb = buf ^ 1;
        As[nb][lkc+0][lrow] = a0.x; As[nb][lkc+1][lrow] = a0.y; As[nb][lkc+2][lrow] = a0.z; As[nb][lkc+3][lrow] = a0.w;
        As[nb][lkc+0][lrow+64] = a1.x; As[nb][lkc+1][lrow+64] = a1.y; As[nb][lkc+2][lrow+64] = a1.z; As[nb][lkc+3][lrow+64] = a1.w;
        Bs[nb][lkc+0][lrow] = b0.x; Bs[nb][lkc+1][lrow] = b0.y; Bs[nb][lkc+2][lrow] = b0.z; Bs[nb][lkc+3][lrow] = b0.w;
        Bs[nb][lkc+0][lrow+64] = b1.x; Bs[nb][lkc+1][lrow+64] = b1.y; Bs[nb][lkc+2][lrow+64] = b1.z; Bs[nb][lkc+3][lrow+64] = b1.w;
        __syncthreads();
        buf = nb;
    }
    // last tile
    #pragma unroll
    for (int kk = 0; kk < 16; kk++) {
        float a[8], b[8];
        *(float4*)&a[0] = *(const float4*)&As[buf][kk][ty * 4];
        *(float4*)&a[4] = *(const float4*)&As[buf][kk][64 + ty * 4];
        *(float4*)&b[0] = *(const float4*)&Bs[buf][kk][tx * 4];
        *(float4*)&b[4] = *(const float4*)&Bs[buf][kk][64 + tx * 4];
        #pragma unroll
        for (int i = 0; i < 8; i++)
            #pragma unroll
            for (int j = 0; j < 8; j++) acc[i][j] += a[i] * b[j];
    }

    #pragma unroll
    for (int i = 0; i < 8; i++) {
        int m = m0 + (i < 4 ? ty * 4 + i : 64 + ty * 4 + (i - 4));
        #pragma unroll
        for (int j = 0; j < 8; j++) {
            int n = n0 + (j < 4 ? tx * 4 + j : 64 + tx * 4 + (j - 4));
            if (n < N) {
                float v = acc[i][j] + (bias ? bias[n] : 0.f);
                if (PERM) {
                    int b = m & (B_ - 1), t = m >> 6;
                    C[((size_t)b * T_ + t) * V_ + n] = v;
                } else {
                    C[(size_t)m * N + n] = v;
                }
            }
        }
    }
}

// ---------------- fused per-step kernel: cell -> att2 -> scores -> softmax -> ctx ------
// All phases for batch b run in block b (no cross-block deps until the gates GEMM).
__global__ void k_step(int t, const float* __restrict__ enc, const float* __restrict__ Wfull,
                       const float* __restrict__ b_ih, const float* __restrict__ b_hh,
                       float* __restrict__ alphas_out) {
    int b = blockIdx.x, tid = threadIdx.x;
    __shared__ float h_sh[256], att2s[256], wfs[256], sc[256], red[256];

    // ---- finish previous step's LSTM cell ----
    if (t > 0) {
        const float* ge = g_gemb + ((size_t)(t - 1) * B_ + b) * NG_;
        float gi = b_ih[tid]       + b_hh[tid]       + ge[tid];
        float gf = b_ih[tid + 256] + b_hh[tid + 256] + ge[tid + 256];
        float gg = b_ih[tid + 512] + b_hh[tid + 512] + ge[tid + 512];
        float go = b_ih[tid + 768] + b_hh[tid + 768] + ge[tid + 768];
        #pragma unroll
        for (int s = 0; s < SPLITK_; s++) {
            const float* gp = g_gpart + ((size_t)s * B_ + b) * NG_;
            gi += gp[tid]; gf += gp[tid + 256]; gg += gp[tid + 512]; go += gp[tid + 768];
        }
        float c  = g_c[b * DEC_ + tid];
        float cn = sigm(gf) * c + sigm(gi) * tanhf(gg);
        float hn = sigm(go) * tanhf(cn);
        g_c[b * DEC_ + tid] = cn;
        g_hall[((size_t)(t - 1) * B_ + b) * DEC_ + tid] = hn;
        h_sh[tid] = hn;
    } else {
        h_sh[tid] = g_h0[b * DEC_ + tid];
    }
    if (t == T_) return;           // final call: only finish last cell

    g_x[b * KX2_ + ENC_ + tid] = h_sh[tid];
    wfs[tid] = Wfull[tid];
    __syncthreads();

    // ---- att2[j] = h . W_dec_att[j,:] (WdaT k-major -> coalesced) ----
    float a2 = 0.f;
    #pragma unroll 8
    for (int k = 0; k < 256; k++) a2 += h_sh[k] * g_WdaT[k * 256 + tid];
    att2s[tid] = a2;
    __syncthreads();

    // ---- scores: warp per p ----
    int lane = tid & 31, wid = tid >> 5;
    for (int p = wid; p < P_; p += 8) {
        const float* row = g_att1 + ((size_t)(b * P_ + p)) * ATT_;
        float s = 0.f;
        #pragma unroll
        for (int a = lane; a < 256; a += 32) {
            float v = row[a] + att2s[a];
            s += fmaxf(v, 0.f) * wfs[a];
        }
        #pragma unroll
        for (int o = 16; o > 0; o >>= 1) s += __shfl_down_sync(0xffffffffu, s, o);
        if (lane == 0) sc[p] = s;
    }
    __syncthreads();

    // ---- softmax over P=196 ----
    float sv = (tid < P_) ? sc[tid] : -1e30f;
    red[tid] = sv;
    __syncthreads();
    for (int s = 128; s > 0; s >>= 1) { if (tid < s) red[tid] = fmaxf(red[tid], red[tid + s]); __syncthreads(); }
    float mx = red[0];
    __syncthreads();
    float ex = (tid < P_) ? expf(sv - mx) : 0.f;
    red[tid] = ex;
    __syncthreads();
    for (int s = 128; s > 0; s >>= 1) { if (tid < s) red[tid] += red[tid + s]; __syncthreads(); }
    float alpha = ex * (1.0f / red[0]);
    __syncthreads();
    sc[tid] = alpha;
    if (tid < P_)
        alphas_out[((size_t)b * T_ + t) * P_ + tid] = alpha;
    __syncthreads();

    // ---- ctx[e] = sum_p alpha[p] * enc[b,p,e]; each thread handles 2 e's ----
    #pragma unroll
    for (int e0 = 0; e0 < 2; e0++) {
        int e = tid + e0 * 256;
        float s = 0.f;
        #pragma unroll 4
        for (int p = 0; p < P_; p++) s += sc[p] * enc[((size_t)(b * P_ + p)) * ENC_ + e];
        g_x[b * KX2_ + e] = s;
    }
}

// ---------------- gates GEMM, split-K over K=768: gpart[sk][b][j] ----------------------
__global__ void k_gates() {
    __shared__ float Xs[64][68];
    __shared__ float Ws[64][68];
    int tid = threadIdx.x;
    int j0 = blockIdx.x * 64;
    int k0 = blockIdx.y * 64;
    #pragma unroll
    for (int r = 0; r < 16; r++) {
        int row = r * 4 + (tid >> 6);
        int k = tid & 63;
        Xs[k][row] = g_x[(size_t)row * KX2_ + k0 + k];
        Ws[k][row] = g_Wcat2[(size_t)(j0 + row) * KX2_ + k0 + k];
    }
    __syncthreads();
    int tx = tid & 15, ty = tid >> 4;
    float acc[4][4] = {};
    #pragma unroll
    for (int kk = 0; kk < 64; kk++) {
        float4 xb = *(const float4*)&Xs[kk][ty * 4];
        float4 wj = *(const float4*)&Ws[kk][tx * 4];
        acc[0][0] += xb.x * wj.x; acc[0][1] += xb.x * wj.y; acc[0][2] += xb.x * wj.z; acc[0][3] += xb.x * wj.w;
        acc[1][0] += xb.y * wj.x; acc[1][1] += xb.y * wj.y; acc[1][2] += xb.y * wj.z; acc[1][3] += xb.y * wj.w;
        acc[2][0] += xb.z * wj.x; acc[2][1] += xb.z * wj.y; acc[2][2] += xb.z * wj.z; acc[2][3] += xb.z * wj.w;
        acc[3][0] += xb.w * wj.x; acc[3][1] += xb.w * wj.y; acc[3][2] += xb.w * wj.z; acc[3][3] += xb.w * wj.w;
    }
    #pragma unroll
    for (int bi = 0; bi < 4; bi++) {
        int b = ty * 4 + bi;
        #pragma unroll
        for (int ji = 0; ji < 4; ji++) {
            g_gpart[((size_t)blockIdx.y * B_ + b) * NG_ + j0 + tx * 4 + ji] = acc[bi][ji];
        }
    }
}

// ---------------- launch ----------------
extern "C" void kernel_launch(void* const* d_in, const int* in_sizes, int n_in,
                              void* d_out, int out_size) {
    const float* enc       = (const float*)d_in[0];
    const int*   caption   = (const int*)  d_in[1];
    const float* W_enc_att = (const float*)d_in[2];
    const float* W_dec_att = (const float*)d_in[3];
    const float* W_full    = (const float*)d_in[4];
    const float* embedding = (const float*)d_in[5];
    const float* W_init_h  = (const float*)d_in[6];
    const float* b_init_h  = (const float*)d_in[7];
    const float* W_init_c  = (const float*)d_in[8];
    const float* b_init_c  = (const float*)d_in[9];
    const float* W_ih      = (const float*)d_in[10];
    const float* b_ih      = (const float*)d_in[11];
    const float* W_hh      = (const float*)d_in[12];
    const float* b_hh      = (const float*)d_in[13];
    const float* W_out     = (const float*)d_in[14];
    const float* b_out     = (const float*)d_in[15];

    float* out    = (float*)d_out;
    float* preds  = out;                              // [B, T, V]
    float* alphas = out + (size_t)B_ * T_ * V_;       // [B, T, P]

    float *att1p, *hallp, *embxp, *wembp, *gembp;
    cudaGetSymbolAddress((void**)&att1p, g_att1);
    cudaGetSymbolAddress((void**)&hallp, g_hall);
    cudaGetSymbolAddress((void**)&embxp, g_embx);
    cudaGetSymbolAddress((void**)&wembp, g_Wemb);
    cudaGetSymbolAddress((void**)&gembp, g_gemb);

    // one-time prep
    int prep_total = NG_ * KX2_ + ATT_ * DEC_ + NG_ * EMB_ + T_ * B_ * EMB_;
    k_prep<<<(prep_total + 255) / 256, 256>>>(W_ih, W_hh, W_dec_att, embedding, caption);
    k_init<<<B_, 256>>>(enc, W_init_h, b_init_h, W_init_c, b_init_c);
    // att1[b,p,a] = enc[b,p,:] . W_enc_att[a,:]   (M=12544, N=256, K=512)
    sgemm128<0><<<dim3(98, 2), 256>>>(enc, W_enc_att, nullptr, att1p, B_ * P_, ATT_, ENC_);
    // gemb[t*B+b][j] = embx . Wemb^T               (M=2816, N=1024, K=256)
    sgemm128<0><<<dim3(22, 8), 256>>>(embxp, wembp, nullptr, gembp, T_ * B_, NG_, EMB_);

    // recurrence: 2 kernels per step
    for (int t = 0; t < T_; t++) {
        k_step<<<B_, 256>>>(t, enc, W_full, b_ih, b_hh, alphas);
        k_gates<<<dim3(NG_ / 64, SPLITK_), 256>>>();
    }
    k_step<<<B_, 256>>>(T_, enc, W_full, b_ih, b_hh, alphas);

    // batched logits: [T*B, DEC] @ W_out^T, permuted store into [B, T, V]
    sgemm128<1><<<dim3((T_ * B_) / 128, (V_ + 127) / 128), 256>>>(hallp, W_out, b_out, preds,
                                                                  T_ * B_, V_, DEC_);
}

// round 5
// speedup vs baseline: 1.8972x; 1.8972x over previous
#include <cuda_runtime.h>
#include <math.h>

#define B_    64
#define P_    196
#define ENC_  512
#define EMB_  256
#define ATT_  256
#define DEC_  256
#define V_    10000
#define T_    44
#define NG_   1024           // 4*DEC
#define KX2_  768            // ENC + DEC (emb part hoisted out of loop)
#define SPLITK_ 12           // gates GEMM K chunks of 64

// ---------------- device scratch (static: no allocation allowed) ----------------
__device__ float g_att1[B_ * P_ * ATT_];        // encoder attention keys
__device__ float g_WdaT[ATT_ * DEC_];           // W_dec_att transposed [k][j]
__device__ float g_Wcat2[NG_ * KX2_];           // [W_ih[:, :512] | W_hh] row-major [j][k]
__device__ float g_Wemb[NG_ * EMB_];            // W_ih[:, 512:768]
__device__ float g_embx[T_ * B_ * EMB_];        // gathered embeddings, all steps
__device__ float g_gemb[T_ * B_ * NG_];         // precomputed emb gate contributions
__device__ float g_h0[B_ * DEC_];
__device__ float g_c[2][B_ * DEC_];             // parity double-buffered cell state
__device__ float g_x[B_ * KX2_];                // per-step LSTM input [ctx | h]
__device__ float g_att2[B_ * ATT_];
__device__ float g_scores[B_ * P_];
__device__ float g_gpart[SPLITK_ * B_ * NG_];   // split-K gate partials
__device__ float g_hall[T_ * B_ * DEC_];        // all hidden states for batched logits

__device__ __forceinline__ float sigm(float x) { return 1.0f / (1.0f + expf(-x)); }

// ---------------- one-time weight prep (transpose / concat / gather) ----------------
__global__ void k_prep(const float* __restrict__ W_ih, const float* __restrict__ W_hh,
                       const float* __restrict__ W_dec_att,
                       const float* __restrict__ embedding, const int* __restrict__ caption) {
    int idx = blockIdx.x * blockDim.x + threadIdx.x;
    if (idx < NG_ * KX2_) {
        int j = idx / KX2_, k = idx % KX2_;
        g_Wcat2[idx] = (k < 512) ? W_ih[j * 768 + k] : W_hh[j * 256 + (k - 512)];
    }
    int i2 = idx - NG_ * KX2_;
    if (i2 >= 0 && i2 < ATT_ * DEC_) {
        int k = i2 >> 8, j = i2 & 255;
        g_WdaT[i2] = W_dec_att[j * 256 + k];
    }
    int i3 = i2 - ATT_ * DEC_;
    if (i3 >= 0 && i3 < NG_ * EMB_) {
        int j = i3 >> 8, k = i3 & 255;
        g_Wemb[i3] = W_ih[j * 768 + 512 + k];
    }
    int i4 = i3 - NG_ * EMB_;
    if (i4 >= 0 && i4 < T_ * B_ * EMB_) {
        int m = i4 >> 8, k = i4 & 255;
        int b = m & (B_ - 1), t = m >> 6;
        g_embx[i4] = embedding[(size_t)caption[b * T_ + t] * EMB_ + k];
    }
}

// ---------------- init h0/c0 from mean-pooled encoder ----------------
__global__ void k_init(const float* __restrict__ enc,
                       const float* __restrict__ W_init_h, const float* __restrict__ b_init_h,
                       const float* __restrict__ W_init_c, const float* __restrict__ b_init_c) {
    int b = blockIdx.x, tid = threadIdx.x;
    __shared__ float avg[ENC_];
    #pragma unroll
    for (int e0 = 0; e0 < 2; e0++) {
        int e = tid + e0 * 256;
        float s = 0.f;
        for (int p = 0; p < P_; p++) s += enc[((size_t)(b * P_ + p)) * ENC_ + e];
        avg[e] = s * (1.0f / (float)P_);
    }
    __syncthreads();
    float h = b_init_h[tid], c = b_init_c[tid];
    const float* wh = W_init_h + (size_t)tid * ENC_;
    const float* wc = W_init_c + (size_t)tid * ENC_;
    #pragma unroll 8
    for (int k = 0; k < ENC_; k++) { h += avg[k] * wh[k]; c += avg[k] * wc[k]; }
    g_h0[b * DEC_ + tid] = h;
    g_c[0][b * DEC_ + tid] = c;   // c_0 lives in parity buffer 0
}

// ---------------- 128x128 tiled SGEMM, 8x8/thread, double-buffered smem ----------------
// C[m][n] = sum_k A[m][k]*Bm[n][k] (+bias)
// PERM=1: row m encodes (t*B + b); store to C[(b*T + t)*V + n] (logits epilogue)
// Requires M % 128 == 0, K % 32 == 0. N guarded.
template<int PERM>
__global__ __launch_bounds__(256) void sgemm128(
        const float* __restrict__ A, const float* __restrict__ Bm,
        const float* __restrict__ bias, float* __restrict__ C,
        int M, int N, int K) {
    __shared__ float As[2][16][132];
    __shared__ float Bs[2][16][132];
    int tid = threadIdx.x;
    int m0 = blockIdx.x * 128, n0 = blockIdx.y * 128;
    int tx = tid & 15, ty = tid >> 4;
    int lrow = tid >> 2;           // 0..63
    int lkc  = (tid & 3) * 4;      // 0,4,8,12

    const float* Ap0 = A + (size_t)(m0 + lrow) * K + lkc;
    const float* Ap1 = A + (size_t)(m0 + lrow + 64) * K + lkc;
    bool bok0 = (n0 + lrow) < N, bok1 = (n0 + lrow + 64) < N;
    const float* Bp0 = Bm + (size_t)(bok0 ? n0 + lrow : 0) * K + lkc;
    const float* Bp1 = Bm + (size_t)(bok1 ? n0 + lrow + 64 : 0) * K + lkc;
    const float4 z4 = make_float4(0.f, 0.f, 0.f, 0.f);

    // initial tile -> buffer 0
    {
        float4 a0 = *(const float4*)Ap0;
        float4 a1 = *(const float4*)Ap1;
        float4 b0 = bok0 ? *(const float4*)Bp0 : z4;
        float4 b1 = bok1 ? *(const float4*)Bp1 : z4;
        As[0][lkc+0][lrow] = a0.x; As[0][lkc+1][lrow] = a0.y; As[0][lkc+2][lrow] = a0.z; As[0][lkc+3][lrow] = a0.w;
        As[0][lkc+0][lrow+64] = a1.x; As[0][lkc+1][lrow+64] = a1.y; As[0][lkc+2][lrow+64] = a1.z; As[0][lkc+3][lrow+64] = a1.w;
        Bs[0][lkc+0][lrow] = b0.x; Bs[0][lkc+1][lrow] = b0.y; Bs[0][lkc+2][lrow] = b0.z; Bs[0][lkc+3][lrow] = b0.w;
        Bs[0][lkc+0][lrow+64] = b1.x; Bs[0][lkc+1][lrow+64] = b1.y; Bs[0][lkc+2][lrow+64] = b1.z; Bs[0][lkc+3][lrow+64] = b1.w;
    }
    __syncthreads();

    float acc[8][8] = {};
    int buf = 0;
    for (int k0 = 16; k0 < K; k0 += 16) {
        float4 a0 = *(const float4*)(Ap0 + k0);
        float4 a1 = *(const float4*)(Ap1 + k0);
        float4 b0 = bok0 ? *(const float4*)(Bp0 + k0) : z4;
        float4 b1 = bok1 ? *(const float4*)(Bp1 + k0) : z4;
        #pragma unroll
        for (int kk = 0; kk < 16; kk++) {
            float a[8], b[8];
            *(float4*)&a[0] = *(const float4*)&As[buf][kk][ty * 4];
            *(float4*)&a[4] = *(const float4*)&As[buf][kk][64 + ty * 4];
            *(float4*)&b[0] = *(const float4*)&Bs[buf][kk][tx * 4];
            *(float4*)&b[4] = *(const float4*)&Bs[buf][kk][64 + tx * 4];
            #pragma unroll
            for (int i = 0; i < 8; i++)
                #pragma unroll
                for (int j = 0; j < 8; j++) acc[i][j] += a[i] * b[j];
        }
        int nb = buf ^ 1;
        As[nb][lkc+0][lrow] = a0.x; As[nb][lkc+1][lrow] = a0.y; As[nb][lkc+2][lrow] = a0.z; As[nb][lkc+3][lrow] = a0.w;
        As[nb][lkc+0][lrow+64] = a1.x; As[nb][lkc+1][lrow+64] = a1.y; As[nb][lkc+2][lrow+64] = a1.z; As[nb][lkc+3][lrow+64] = a1.w;
        Bs[nb][lkc+0][lrow] = b0.x; Bs[nb][lkc+1][lrow] = b0.y; Bs[nb][lkc+2][lrow] = b0.z; Bs[nb][lkc+3][lrow] = b0.w;
        Bs[nb][lkc+0][lrow+64] = b1.x; Bs[nb][lkc+1][lrow+64] = b1.y; Bs[nb][lkc+2][lrow+64] = b1.z; Bs[nb][lkc+3][lrow+64] = b1.w;
        __syncthreads();
        buf = nb;
    }
    #pragma unroll
    for (int kk = 0; kk < 16; kk++) {
        float a[8], b[8];
        *(float4*)&a[0] = *(const float4*)&As[buf][kk][ty * 4];
        *(float4*)&a[4] = *(const float4*)&As[buf][kk][64 + ty * 4];
        *(float4*)&b[0] = *(const float4*)&Bs[buf][kk][tx * 4];
        *(float4*)&b[4] = *(const float4*)&Bs[buf][kk][64 + tx * 4];
        #pragma unroll
        for (int i = 0; i < 8; i++)
            #pragma unroll
            for (int j = 0; j < 8; j++) acc[i][j] += a[i] * b[j];
    }

    #pragma unroll
    for (int i = 0; i < 8; i++) {
        int m = m0 + (i < 4 ? ty * 4 + i : 64 + ty * 4 + (i - 4));
        #pragma unroll
        for (int j = 0; j < 8; j++) {
            int n = n0 + (j < 4 ? tx * 4 + j : 64 + tx * 4 + (j - 4));
            if (n < N) {
                float v = acc[i][j] + (bias ? bias[n] : 0.f);
                if (PERM) {
                    int b = m & (B_ - 1), t = m >> 6;
                    C[((size_t)b * T_ + t) * V_ + n] = v;
                } else {
                    C[(size_t)m * N + n] = v;
                }
            }
        }
    }
}

// ---------------- cell body (shared by k_scores_cell / k_cell_final) -------------------
// Finishes step (t-1)'s LSTM cell. Reads c from parity (t-1)&1, writes parity t&1.
// Safe to run redundantly in multiple blocks: all write identical values.
__device__ __forceinline__ void cell_body(int t, int b, int tid,
                                          const float* __restrict__ b_ih,
                                          const float* __restrict__ b_hh,
                                          float* h_sh) {
    const float* ge = g_gemb + ((size_t)(t - 1) * B_ + b) * NG_;
    float gi = b_ih[tid]       + b_hh[tid]       + ge[tid];
    float gf = b_ih[tid + 256] + b_hh[tid + 256] + ge[tid + 256];
    float gg = b_ih[tid + 512] + b_hh[tid + 512] + ge[tid + 512];
    float go = b_ih[tid + 768] + b_hh[tid + 768] + ge[tid + 768];
    #pragma unroll
    for (int s = 0; s < SPLITK_; s++) {
        const float* gp = g_gpart + ((size_t)s * B_ + b) * NG_;
        gi += gp[tid]; gf += gp[tid + 256]; gg += gp[tid + 512]; go += gp[tid + 768];
    }
    float c  = g_c[(t - 1) & 1][b * DEC_ + tid];
    float cn = sigm(gf) * c + sigm(gi) * tanhf(gg);
    float hn = sigm(go) * tanhf(cn);
    g_c[t & 1][b * DEC_ + tid] = cn;
    g_hall[((size_t)(t - 1) * B_ + b) * DEC_ + tid] = hn;
    if (h_sh) h_sh[tid] = hn;
}

// ---------------- per-step kernel 1: (redundant) cell + att2, then 28 scores ----------
// grid (B, 7). Each block redundantly finishes the cell and computes att2 for its b
// (identical values in all 7 y-blocks -> duplicate identical writes are deterministic),
// then computes its 28 attention scores.
__global__ void k_scores_cell(int t, const float* __restrict__ Wfull,
                              const float* __restrict__ b_ih, const float* __restrict__ b_hh) {
    int b = blockIdx.x, tid = threadIdx.x;
    int p0 = blockIdx.y * 28;
    __shared__ float h_sh[256], att2s[256], wfs[256];

    if (t > 0) cell_body(t, b, tid, b_ih, b_hh, h_sh);
    else       h_sh[tid] = g_h0[b * DEC_ + tid];
    if (blockIdx.y == 0) g_x[b * KX2_ + ENC_ + tid] = h_sh[tid];
    wfs[tid] = Wfull[tid];
    __syncthreads();

    // att2[j] = h . W_dec_att[j,:]  (WdaT k-major -> coalesced, L2-resident)
    float a2 = 0.f;
    #pragma unroll 8
    for (int k = 0; k < 256; k++) a2 += h_sh[k] * g_WdaT[k * 256 + tid];
    att2s[tid] = a2;
    __syncthreads();

    int lane = tid & 31, wid = tid >> 5;
    for (int p = p0 + wid; p < p0 + 28; p += 8) {
        const float* row = g_att1 + ((size_t)(b * P_ + p)) * ATT_;
        float s = 0.f;
        #pragma unroll
        for (int a = lane; a < 256; a += 32) {
            float v = row[a] + att2s[a];
            s += fmaxf(v, 0.f) * wfs[a];
        }
        #pragma unroll
        for (int o = 16; o > 0; o >>= 1) s += __shfl_down_sync(0xffffffffu, s, o);
        if (lane == 0) g_scores[b * P_ + p] = s;
    }
}

// ---------------- final cell only (after last step's gates) ----------------------------
__global__ void k_cell_final(const float* __restrict__ b_ih, const float* __restrict__ b_hh) {
    cell_body(T_, blockIdx.x, threadIdx.x, b_ih, b_hh, nullptr);
}

// ---------------- per-step kernel 2: softmax (recomputed per block) + 64-e ctx chunk ---
__global__ void k_softmax_ctx(int t, const float* __restrict__ enc,
                              float* __restrict__ alphas_out) {
    int b = blockIdx.x, tid = threadIdx.x;
    int e0 = blockIdx.y * 64;
    __shared__ float sc[256], red[256];
    float sv = (tid < P_) ? g_scores[b * P_ + tid] : -1e30f;
    red[tid] = sv;
    __syncthreads();
    for (int s = 128; s > 0; s >>= 1) { if (tid < s) red[tid] = fmaxf(red[tid], red[tid + s]); __syncthreads(); }
    float mx = red[0];
    __syncthreads();
    float ex = (tid < P_) ? expf(sv - mx) : 0.f;
    red[tid] = ex;
    __syncthreads();
    for (int s = 128; s > 0; s >>= 1) { if (tid < s) red[tid] += red[tid + s]; __syncthreads(); }
    float inv = 1.0f / red[0];
    float alpha = ex * inv;
    sc[tid] = alpha;
    if (blockIdx.y == 0 && tid < P_)
        alphas_out[((size_t)b * T_ + t) * P_ + tid] = alpha;
    __syncthreads();
    // ctx: 64 e's, 4 threads per e
    int e = tid & 63, ps = tid >> 6;
    float s = 0.f;
    for (int p = ps; p < P_; p += 4)
        s += sc[p] * enc[((size_t)(b * P_ + p)) * ENC_ + e0 + e];
    red[tid] = s;
    __syncthreads();
    if (tid < 64)
        g_x[b * KX2_ + e0 + tid] = red[tid] + red[tid + 64] + red[tid + 128] + red[tid + 192];
}

// ---------------- per-step kernel 3: gates GEMM, split-K over K=768 --------------------
__global__ void k_gates() {
    __shared__ float Xs[64][68];
    __shared__ float Ws[64][68];
    int tid = threadIdx.x;
    int j0 = blockIdx.x * 64;
    int k0 = blockIdx.y * 64;
    #pragma unroll
    for (int r = 0; r < 16; r++) {
        int row = r * 4 + (tid >> 6);
        int k = tid & 63;
        Xs[k][row] = g_x[(size_t)row * KX2_ + k0 + k];
        Ws[k][row] = g_Wcat2[(size_t)(j0 + row) * KX2_ + k0 + k];
    }
    __syncthreads();
    int tx = tid & 15, ty = tid >> 4;
    float acc[4][4] = {};
    #pragma unroll
    for (int kk = 0; kk < 64; kk++) {
        float4 xb = *(const float4*)&Xs[kk][ty * 4];
        float4 wj = *(const float4*)&Ws[kk][tx * 4];
        acc[0][0] += xb.x * wj.x; acc[0][1] += xb.x * wj.y; acc[0][2] += xb.x * wj.z; acc[0][3] += xb.x * wj.w;
        acc[1][0] += xb.y * wj.x; acc[1][1] += xb.y * wj.y; acc[1][2] += xb.y * wj.z; acc[1][3] += xb.y * wj.w;
        acc[2][0] += xb.z * wj.x; acc[2][1] += xb.z * wj.y; acc[2][2] += xb.z * wj.z; acc[2][3] += xb.z * wj.w;
        acc[3][0] += xb.w * wj.x; acc[3][1] += xb.w * wj.y; acc[3][2] += xb.w * wj.z; acc[3][3] += xb.w * wj.w;
    }
    #pragma unroll
    for (int bi = 0; bi < 4; bi++) {
        int b = ty * 4 + bi;
        #pragma unroll
        for (int ji = 0; ji < 4; ji++) {
            g_gpart[((size_t)blockIdx.y * B_ + b) * NG_ + j0 + tx * 4 + ji] = acc[bi][ji];
        }
    }
}

// ---------------- launch ----------------
extern "C" void kernel_launch(void* const* d_in, const int* in_sizes, int n_in,
                              void* d_out, int out_size) {
    const float* enc       = (const float*)d_in[0];
    const int*   caption   = (const int*)  d_in[1];
    const float* W_enc_att = (const float*)d_in[2];
    const float* W_dec_att = (const float*)d_in[3];
    const float* W_full    = (const float*)d_in[4];
    const float* embedding = (const float*)d_in[5];
    const float* W_init_h  = (const float*)d_in[6];
    const float* b_init_h  = (const float*)d_in[7];
    const float* W_init_c  = (const float*)d_in[8];
    const float* b_init_c  = (const float*)d_in[9];
    const float* W_ih      = (const float*)d_in[10];
    const float* b_ih      = (const float*)d_in[11];
    const float* W_hh      = (const float*)d_in[12];
    const float* b_hh      = (const float*)d_in[13];
    const float* W_out     = (const float*)d_in[14];
    const float* b_out     = (const float*)d_in[15];

    float* out    = (float*)d_out;
    float* preds  = out;                              // [B, T, V]
    float* alphas = out + (size_t)B_ * T_ * V_;       // [B, T, P]

    float *att1p, *hallp, *embxp, *wembp, *gembp;
    cudaGetSymbolAddress((void**)&att1p, g_att1);
    cudaGetSymbolAddress((void**)&hallp, g_hall);
    cudaGetSymbolAddress((void**)&embxp, g_embx);
    cudaGetSymbolAddress((void**)&wembp, g_Wemb);
    cudaGetSymbolAddress((void**)&gembp, g_gemb);

    // one-time prep
    int prep_total = NG_ * KX2_ + ATT_ * DEC_ + NG_ * EMB_ + T_ * B_ * EMB_;
    k_prep<<<(prep_total + 255) / 256, 256>>>(W_ih, W_hh, W_dec_att, embedding, caption);
    k_init<<<B_, 256>>>(enc, W_init_h, b_init_h, W_init_c, b_init_c);
    // att1[b,p,a] = enc[b,p,:] . W_enc_att[a,:]   (M=12544, N=256, K=512)
    sgemm128<0><<<dim3(98, 2), 256>>>(enc, W_enc_att, nullptr, att1p, B_ * P_, ATT_, ENC_);
    // gemb[t*B+b][j] = embx . Wemb^T               (M=2816, N=1024, K=256)
    sgemm128<0><<<dim3(22, 8), 256>>>(embxp, wembp, nullptr, gembp, T_ * B_, NG_, EMB_);

    // recurrence: 3 wide kernels per step
    for (int t = 0; t < T_; t++) {
        k_scores_cell<<<dim3(B_, 7), 256>>>(t, W_full, b_ih, b_hh);
        k_softmax_ctx<<<dim3(B_, 8), 256>>>(t, enc, alphas);
        k_gates<<<dim3(NG_ / 64, SPLITK_), 256>>>();
    }
    k_cell_final<<<B_, 256>>>(b_ih, b_hh);

    // batched logits: [T*B, DEC] @ W_out^T, permuted store into [B, T, V]
    sgemm128<1><<<dim3((T_ * B_) / 128, (V_ + 127) / 128), 256>>>(hallp, W_out, b_out, preds,
                                                                  T_ * B_, V_, DEC_);
}

// round 8
// speedup vs baseline: 1.9214x; 1.0128x over previous
#include <cuda_runtime.h>
#include <mma.h>
#include <math.h>

using namespace nvcuda;

#define B_    64
#define P_    196
#define ENC_  512
#define EMB_  256
#define ATT_  256
#define DEC_  256
#define V_    10000
#define T_    44
#define NG_   1024           // 4*DEC
#define KX2_  768            // ENC + DEC (emb part hoisted out of loop)
#define SPLITK_ 12           // gates GEMM K chunks of 64

// ---------------- device scratch (static: no allocation allowed) ----------------
__device__ float g_att1[B_ * P_ * ATT_];        // encoder attention keys
__device__ float g_WdaT[ATT_ * DEC_];           // W_dec_att transposed [k][j]
__device__ float g_Wcat2[NG_ * KX2_];           // [W_ih[:, :512] | W_hh] row-major [j][k]
__device__ float g_Wemb[NG_ * EMB_];            // W_ih[:, 512:768]
__device__ float g_embx[T_ * B_ * EMB_];        // gathered embeddings, all steps
__device__ float g_gemb[T_ * B_ * NG_];         // precomputed emb gate contributions
__device__ float g_h0[B_ * DEC_];
__device__ float g_c[2][B_ * DEC_];             // parity double-buffered cell state
__device__ float g_x[B_ * KX2_];                // per-step LSTM input [ctx | h]
__device__ float g_scores[B_ * P_];
__device__ float g_gpart[SPLITK_ * B_ * NG_];   // split-K gate partials
__device__ float g_hall[T_ * B_ * DEC_];        // all hidden states for batched logits

__device__ __forceinline__ float sigm(float x) { return 1.0f / (1.0f + expf(-x)); }

// ---------------- one-time weight prep (transpose / concat / gather) ----------------
__global__ void k_prep(const float* __restrict__ W_ih, const float* __restrict__ W_hh,
                       const float* __restrict__ W_dec_att,
                       const float* __restrict__ embedding, const int* __restrict__ caption) {
    int idx = blockIdx.x * blockDim.x + threadIdx.x;
    if (idx < NG_ * KX2_) {
        int j = idx / KX2_, k = idx % KX2_;
        g_Wcat2[idx] = (k < 512) ? W_ih[j * 768 + k] : W_hh[j * 256 + (k - 512)];
    }
    int i2 = idx - NG_ * KX2_;
    if (i2 >= 0 && i2 < ATT_ * DEC_) {
        int k = i2 >> 8, j = i2 & 255;
        g_WdaT[i2] = W_dec_att[j * 256 + k];
    }
    int i3 = i2 - ATT_ * DEC_;
    if (i3 >= 0 && i3 < NG_ * EMB_) {
        int j = i3 >> 8, k = i3 & 255;
        g_Wemb[i3] = W_ih[j * 768 + 512 + k];
    }
    int i4 = i3 - NG_ * EMB_;
    if (i4 >= 0 && i4 < T_ * B_ * EMB_) {
        int m = i4 >> 8, k = i4 & 255;
        int b = m & (B_ - 1), t = m >> 6;
        g_embx[i4] = embedding[(size_t)caption[b * T_ + t] * EMB_ + k];
    }
}

// ---------------- init h0/c0 from mean-pooled encoder ----------------
__global__ void k_init(const float* __restrict__ enc,
                       const float* __restrict__ W_init_h, const float* __restrict__ b_init_h,
                       const float* __restrict__ W_init_c, const float* __restrict__ b_init_c) {
    int b = blockIdx.x, tid = threadIdx.x;
    __shared__ float avg[ENC_];
    #pragma unroll
    for (int e0 = 0; e0 < 2; e0++) {
        int e = tid + e0 * 256;
        float s = 0.f;
        for (int p = 0; p < P_; p++) s += enc[((size_t)(b * P_ + p)) * ENC_ + e];
        avg[e] = s * (1.0f / (float)P_);
    }
    __syncthreads();
    float h = b_init_h[tid], c = b_init_c[tid];
    const float* wh = W_init_h + (size_t)tid * ENC_;
    const float* wc = W_init_c + (size_t)tid * ENC_;
    #pragma unroll 8
    for (int k = 0; k < ENC_; k++) { h += avg[k] * wh[k]; c += avg[k] * wc[k]; }
    g_h0[b * DEC_ + tid] = h;
    g_c[0][b * DEC_ + tid] = c;   // c_0 lives in parity buffer 0
}

// ---------------- 128x128 tiled SGEMM, 8x8/thread, double-buffered smem ----------------
// C[m][n] = sum_k A[m][k]*Bm[n][k] (+bias). fp32. Used for att1/gemb (feed recurrence).
template<int PERM>
__global__ __launch_bounds__(256) void sgemm128(
        const float* __restrict__ A, const float* __restrict__ Bm,
        const float* __restrict__ bias, float* __restrict__ C,
        int M, int N, int K) {
    __shared__ float As[2][16][132];
    __shared__ float Bs[2][16][132];
    int tid = threadIdx.x;
    int m0 = blockIdx.x * 128, n0 = blockIdx.y * 128;
    int tx = tid & 15, ty = tid >> 4;
    int lrow = tid >> 2;           // 0..63
    int lkc  = (tid & 3) * 4;      // 0,4,8,12

    const float* Ap0 = A + (size_t)(m0 + lrow) * K + lkc;
    const float* Ap1 = A + (size_t)(m0 + lrow + 64) * K + lkc;
    bool bok0 = (n0 + lrow) < N, bok1 = (n0 + lrow + 64) < N;
    const float* Bp0 = Bm + (size_t)(bok0 ? n0 + lrow : 0) * K + lkc;
    const float* Bp1 = Bm + (size_t)(bok1 ? n0 + lrow + 64 : 0) * K + lkc;
    const float4 z4 = make_float4(0.f, 0.f, 0.f, 0.f);

    {
        float4 a0 = *(const float4*)Ap0;
        float4 a1 = *(const float4*)Ap1;
        float4 b0 = bok0 ? *(const float4*)Bp0 : z4;
        float4 b1 = bok1 ? *(const float4*)Bp1 : z4;
        As[0][lkc+0][lrow] = a0.x; As[0][lkc+1][lrow] = a0.y; As[0][lkc+2][lrow] = a0.z; As[0][lkc+3][lrow] = a0.w;
        As[0][lkc+0][lrow+64] = a1.x; As[0][lkc+1][lrow+64] = a1.y; As[0][lkc+2][lrow+64] = a1.z; As[0][lkc+3][lrow+64] = a1.w;
        Bs[0][lkc+0][lrow] = b0.x; Bs[0][lkc+1][lrow] = b0.y; Bs[0][lkc+2][lrow] = b0.z; Bs[0][lkc+3][lrow] = b0.w;
        Bs[0][lkc+0][lrow+64] = b1.x; Bs[0][lkc+1][lrow+64] = b1.y; Bs[0][lkc+2][lrow+64] = b1.z; Bs[0][lkc+3][lrow+64] = b1.w;
    }
    __syncthreads();

    float acc[8][8] = {};
    int buf = 0;
    for (int k0 = 16; k0 < K; k0 += 16) {
        float4 a0 = *(const float4*)(Ap0 + k0);
        float4 a1 = *(const float4*)(Ap1 + k0);
        float4 b0 = bok0 ? *(const float4*)(Bp0 + k0) : z4;
        float4 b1 = bok1 ? *(const float4*)(Bp1 + k0) : z4;
        #pragma unroll
        for (int kk = 0; kk < 16; kk++) {
            float a[8], b[8];
            *(float4*)&a[0] = *(const float4*)&As[buf][kk][ty * 4];
            *(float4*)&a[4] = *(const float4*)&As[buf][kk][64 + ty * 4];
            *(float4*)&b[0] = *(const float4*)&Bs[buf][kk][tx * 4];
            *(float4*)&b[4] = *(const float4*)&Bs[buf][kk][64 + tx * 4];
            #pragma unroll
            for (int i = 0; i < 8; i++)
                #pragma unroll
                for (int j = 0; j < 8; j++) acc[i][j] += a[i] * b[j];
        }
        int nb = buf ^ 1;
        As[nb][lkc+0][lrow] = a0.x; As[nb][lkc+1][lrow] = a0.y; As[nb][lkc+2][lrow] = a0.z; As[nb][lkc+3][lrow] = a0.w;
        As[nb][lkc+0][lrow+64] = a1.x; As[nb][lkc+1][lrow+64] = a1.y; As[nb][lkc+2][lrow+64] = a1.z; As[nb][lkc+3][lrow+64] = a1.w;
        Bs[nb][lkc+0][lrow] = b0.x; Bs[nb][lkc+1][lrow] = b0.y; Bs[nb][lkc+2][lrow] = b0.z; Bs[nb][lkc+3][lrow] = b0.w;
        Bs[nb][lkc+0][lrow+64] = b1.x; Bs[nb][lkc+1][lrow+64] = b1.y; Bs[nb][lkc+2][lrow+64] = b1.z; Bs[nb][lkc+3][lrow+64] = b1.w;
        __syncthreads();
        buf = nb;
    }
    #pragma unroll
    for (int kk = 0; kk < 16; kk++) {
        float a[8], b[8];
        *(float4*)&a[0] = *(const float4*)&As[buf][kk][ty * 4];
        *(float4*)&a[4] = *(const float4*)&As[buf][kk][64 + ty * 4];
        *(float4*)&b[0] = *(const float4*)&Bs[buf][kk][tx * 4];
        *(float4*)&b[4] = *(const float4*)&Bs[buf][kk][64 + tx * 4];
        #pragma unroll
        for (int i = 0; i < 8; i++)
            #pragma unroll
            for (int j = 0; j < 8; j++) acc[i][j] += a[i] * b[j];
    }

    #pragma unroll
    for (int i = 0; i < 8; i++) {
        int m = m0 + (i < 4 ? ty * 4 + i : 64 + ty * 4 + (i - 4));
        #pragma unroll
        for (int j = 0; j < 8; j++) {
            int n = n0 + (j < 4 ? tx * 4 + j : 64 + tx * 4 + (j - 4));
            if (n < N) {
                float v = acc[i][j] + (bias ? bias[n] : 0.f);
                if (PERM) {
                    int b = m & (B_ - 1), t = m >> 6;
                    C[((size_t)b * T_ + t) * V_ + n] = v;
                } else {
                    C[(size_t)m * N + n] = v;
                }
            }
        }
    }
}

// ================= WMMA tf32 GEMM (HMMA pipe; compute_103-baseline safe) ===============
// C[m][n] = sum_k A[m][k]*Bm[n][k] (+bias), tf32 inputs, fp32 accumulate.
// CTA 128x128, 8 warps (4m x 2n), warp tile 32x64 = 2x4 wmma m16n16k8 frags.
// PERM=1: row m encodes (t*B + b); store to C[(b*T + t)*V + n].
// NOTE: all WMMA ld/st leading dims are multiples of 4 elements (API requirement).
#define WG_KPAD 20
#define EPI_LD  20

template<int PERM>
__global__ __launch_bounds__(256) void wgemm(
        const float* __restrict__ A, const float* __restrict__ Bm,
        const float* __restrict__ bias, float* __restrict__ C,
        int M, int N, int K) {
    __shared__ float As[128][WG_KPAD];
    __shared__ float Bs[128][WG_KPAD];
    __shared__ float epi[8][16][EPI_LD];
    int tid = threadIdx.x;
    int wid = tid >> 5, lane = tid & 31;
    int wm = wid & 3, wn = wid >> 2;          // warp tile: rows wm*32, cols wn*64
    int m0 = blockIdx.x * 128, n0 = blockIdx.y * 128;

    wmma::fragment<wmma::accumulator, 16, 16, 8, float> acc[2][4];
    #pragma unroll
    for (int mi = 0; mi < 2; mi++)
        #pragma unroll
        for (int ni = 0; ni < 4; ni++) wmma::fill_fragment(acc[mi][ni], 0.f);

    int lrow = tid >> 2;           // 0..63
    int lk = (tid & 3) * 4;        // 0,4,8,12
    bool bok0 = (n0 + lrow) < N, bok1 = (n0 + lrow + 64) < N;
    const float4 z4 = make_float4(0.f, 0.f, 0.f, 0.f);

    for (int k0 = 0; k0 < K; k0 += 16) {
        float4 a0 = *(const float4*)&A[(size_t)(m0 + lrow) * K + k0 + lk];
        float4 a1 = *(const float4*)&A[(size_t)(m0 + lrow + 64) * K + k0 + lk];
        float4 b0 = bok0 ? *(const float4*)&Bm[(size_t)(n0 + lrow) * K + k0 + lk] : z4;
        float4 b1 = bok1 ? *(const float4*)&Bm[(size_t)(n0 + lrow + 64) * K + k0 + lk] : z4;
        *(float4*)&As[lrow][lk] = a0;
        *(float4*)&As[lrow + 64][lk] = a1;
        *(float4*)&Bs[lrow][lk] = b0;
        *(float4*)&Bs[lrow + 64][lk] = b1;
        __syncthreads();

        #pragma unroll
        for (int ks = 0; ks < 2; ks++) {
            wmma::fragment<wmma::matrix_a, 16, 16, 8, wmma::precision::tf32, wmma::row_major> af[2];
            wmma::fragment<wmma::matrix_b, 16, 16, 8, wmma::precision::tf32, wmma::col_major> bf[4];
            #pragma unroll
            for (int mi = 0; mi < 2; mi++) {
                wmma::load_matrix_sync(af[mi], &As[wm * 32 + mi * 16][ks * 8], WG_KPAD);
                #pragma unroll
                for (int e = 0; e < af[mi].num_elements; e++)
                    af[mi].x[e] = wmma::__float_to_tf32(af[mi].x[e]);
            }
            #pragma unroll
            for (int ni = 0; ni < 4; ni++) {
                wmma::load_matrix_sync(bf[ni], &Bs[wn * 64 + ni * 16][ks * 8], WG_KPAD);
                #pragma unroll
                for (int e = 0; e < bf[ni].num_elements; e++)
                    bf[ni].x[e] = wmma::__float_to_tf32(bf[ni].x[e]);
            }
            #pragma unroll
            for (int mi = 0; mi < 2; mi++)
                #pragma unroll
                for (int ni = 0; ni < 4; ni++)
                    wmma::mma_sync(acc[mi][ni], af[mi], bf[ni], acc[mi][ni]);
        }
        __syncthreads();
    }

    // epilogue: stage each 16x16 accumulator through SMEM for bias + permuted store
    #pragma unroll
    for (int mi = 0; mi < 2; mi++) {
        #pragma unroll
        for (int ni = 0; ni < 4; ni++) {
            wmma::store_matrix_sync(&epi[wid][0][0], acc[mi][ni], EPI_LD, wmma::mem_row_major);
            __syncwarp();
            int mbase = m0 + wm * 32 + mi * 16;
            int nbase = n0 + wn * 64 + ni * 16;
            int r = lane >> 1, c0 = (lane & 1) * 8;
            int m = mbase + r;
            size_t rowbase;
            if (PERM) {
                int b = m & (B_ - 1), t = m >> 6;
                rowbase = ((size_t)b * T_ + t) * (size_t)V_;
            } else {
                rowbase = (size_t)m * (size_t)N;
            }
            #pragma unroll
            for (int c = 0; c < 8; c++) {
                int n = nbase + c0 + c;
                if (n < N)
                    C[rowbase + n] = epi[wid][r][c0 + c] + (bias ? bias[n] : 0.f);
            }
            __syncwarp();
        }
    }
}

// ---------------- cell body: finishes step (t-1)'s LSTM cell ---------------------------
__device__ __forceinline__ void cell_body(int t, int b, int tid,
                                          const float* __restrict__ b_ih,
                                          const float* __restrict__ b_hh,
                                          float* h_sh) {
    const float* ge = g_gemb + ((size_t)(t - 1) * B_ + b) * NG_;
    float gi = b_ih[tid]       + b_hh[tid]       + ge[tid];
    float gf = b_ih[tid + 256] + b_hh[tid + 256] + ge[tid + 256];
    float gg = b_ih[tid + 512] + b_hh[tid + 512] + ge[tid + 512];
    float go = b_ih[tid + 768] + b_hh[tid + 768] + ge[tid + 768];
    #pragma unroll
    for (int s = 0; s < SPLITK_; s++) {
        const float* gp = g_gpart + ((size_t)s * B_ + b) * NG_;
        gi += gp[tid]; gf += gp[tid + 256]; gg += gp[tid + 512]; go += gp[tid + 768];
    }
    float c  = g_c[(t - 1) & 1][b * DEC_ + tid];
    float cn = sigm(gf) * c + sigm(gi) * tanhf(gg);
    float hn = sigm(go) * tanhf(cn);
    g_c[t & 1][b * DEC_ + tid] = cn;
    g_hall[((size_t)(t - 1) * B_ + b) * DEC_ + tid] = hn;
    if (h_sh) h_sh[tid] = hn;
}

// ---------------- per-step kernel 1: (redundant) cell + att2, then 28 scores ----------
__global__ void k_scores_cell(int t, const float* __restrict__ Wfull,
                              const float* __restrict__ b_ih, const float* __restrict__ b_hh) {
    int b = blockIdx.x, tid = threadIdx.x;
    int p0 = blockIdx.y * 28;
    __shared__ float h_sh[256], att2s[256], wfs[256];

    if (t > 0) cell_body(t, b, tid, b_ih, b_hh, h_sh);
    else       h_sh[tid] = g_h0[b * DEC_ + tid];
    if (blockIdx.y == 0) g_x[b * KX2_ + ENC_ + tid] = h_sh[tid];
    wfs[tid] = Wfull[tid];
    __syncthreads();

    float a2 = 0.f;
    #pragma unroll 8
    for (int k = 0; k < 256; k++) a2 += h_sh[k] * g_WdaT[k * 256 + tid];
    att2s[tid] = a2;
    __syncthreads();

    int lane = tid & 31, wid = tid >> 5;
    for (int p = p0 + wid; p < p0 + 28; p += 8) {
        const float* row = g_att1 + ((size_t)(b * P_ + p)) * ATT_;
        float s = 0.f;
        #pragma unroll
        for (int a = lane; a < 256; a += 32) {
            float v = row[a] + att2s[a];
            s += fmaxf(v, 0.f) * wfs[a];
        }
        #pragma unroll
        for (int o = 16; o > 0; o >>= 1) s += __shfl_down_sync(0xffffffffu, s, o);
        if (lane == 0) g_scores[b * P_ + p] = s;
    }
}

// ---------------- final cell only (after last step's gates) ----------------------------
__global__ void k_cell_final(const float* __restrict__ b_ih, const float* __restrict__ b_hh) {
    cell_body(T_, blockIdx.x, threadIdx.x, b_ih, b_hh, nullptr);
}

// ---------------- per-step kernel 2: softmax (recomputed per block) + 64-e ctx chunk ---
__global__ void k_softmax_ctx(int t, const float* __restrict__ enc,
                              float* __restrict__ alphas_out) {
    int b = blockIdx.x, tid = threadIdx.x;
    int e0 = blockIdx.y * 64;
    __shared__ float sc[256], red[256];
    float sv = (tid < P_) ? g_scores[b * P_ + tid] : -1e30f;
    red[tid] = sv;
    __syncthreads();
    for (int s = 128; s > 0; s >>= 1) { if (tid < s) red[tid] = fmaxf(red[tid], red[tid + s]); __syncthreads(); }
    float mx = red[0];
    __syncthreads();
    float ex = (tid < P_) ? expf(sv - mx) : 0.f;
    red[tid] = ex;
    __syncthreads();
    for (int s = 128; s > 0; s >>= 1) { if (tid < s) red[tid] += red[tid + s]; __syncthreads(); }
    float inv = 1.0f / red[0];
    float alpha = ex * inv;
    sc[tid] = alpha;
    if (blockIdx.y == 0 && tid < P_)
        alphas_out[((size_t)b * T_ + t) * P_ + tid] = alpha;
    __syncthreads();
    int e = tid & 63, ps = tid >> 6;
    float s = 0.f;
    for (int p = ps; p < P_; p += 4)
        s += sc[p] * enc[((size_t)(b * P_ + p)) * ENC_ + e0 + e];
    red[tid] = s;
    __syncthreads();
    if (tid < 64)
        g_x[b * KX2_ + e0 + tid] = red[tid] + red[tid + 64] + red[tid + 128] + red[tid + 192];
}

// ---------------- per-step kernel 3: gates GEMM, split-K over K=768 --------------------
__global__ void k_gates() {
    __shared__ float Xs[64][68];
    __shared__ float Ws[64][68];
    int tid = threadIdx.x;
    int j0 = blockIdx.x * 64;
    int k0 = blockIdx.y * 64;
    #pragma unroll
    for (int r = 0; r < 16; r++) {
        int row = r * 4 + (tid >> 6);
        int k = tid & 63;
        Xs[k][row] = g_x[(size_t)row * KX2_ + k0 + k];
        Ws[k][row] = g_Wcat2[(size_t)(j0 + row) * KX2_ + k0 + k];
    }
    __syncthreads();
    int tx = tid & 15, ty = tid >> 4;
    float acc[4][4] = {};
    #pragma unroll
    for (int kk = 0; kk < 64; kk++) {
        float4 xb = *(const float4*)&Xs[kk][ty * 4];
        float4 wj = *(const float4*)&Ws[kk][tx * 4];
        acc[0][0] += xb.x * wj.x; acc[0][1] += xb.x * wj.y; acc[0][2] += xb.x * wj.z; acc[0][3] += xb.x * wj.w;
        acc[1][0] += xb.y * wj.x; acc[1][1] += xb.y * wj.y; acc[1][2] += xb.y * wj.z; acc[1][3] += xb.y * wj.w;
        acc[2][0] += xb.z * wj.x; acc[2][1] += xb.z * wj.y; acc[2][2] += xb.z * wj.z; acc[2][3] += xb.z * wj.w;
        acc[3][0] += xb.w * wj.x; acc[3][1] += xb.w * wj.y; acc[3][2] += xb.w * wj.z; acc[3][3] += xb.w * wj.w;
    }
    #pragma unroll
    for (int bi = 0; bi < 4; bi++) {
        int b = ty * 4 + bi;
        #pragma unroll
        for (int ji = 0; ji < 4; ji++) {
            g_gpart[((size_t)blockIdx.y * B_ + b) * NG_ + j0 + tx * 4 + ji] = acc[bi][ji];
        }
    }
}

// ---------------- launch ----------------
extern "C" void kernel_launch(void* const* d_in, const int* in_sizes, int n_in,
                              void* d_out, int out_size) {
    const float* enc       = (const float*)d_in[0];
    const int*   caption   = (const int*)  d_in[1];
    const float* W_enc_att = (const float*)d_in[2];
    const float* W_dec_att = (const float*)d_in[3];
    const float* W_full    = (const float*)d_in[4];
    const float* embedding = (const float*)d_in[5];
    const float* W_init_h  = (const float*)d_in[6];
    const float* b_init_h  = (const float*)d_in[7];
    const float* W_init_c  = (const float*)d_in[8];
    const float* b_init_c  = (const float*)d_in[9];
    const float* W_ih      = (const float*)d_in[10];
    const float* b_ih      = (const float*)d_in[11];
    const float* W_hh      = (const float*)d_in[12];
    const float* b_hh      = (const float*)d_in[13];
    const float* W_out     = (const float*)d_in[14];
    const float* b_out     = (const float*)d_in[15];

    float* out    = (float*)d_out;
    float* preds  = out;                              // [B, T, V]
    float* alphas = out + (size_t)B_ * T_ * V_;       // [B, T, P]

    float *att1p, *hallp, *embxp, *wembp, *gembp;
    cudaGetSymbolAddress((void**)&att1p, g_att1);
    cudaGetSymbolAddress((void**)&hallp, g_hall);
    cudaGetSymbolAddress((void**)&embxp, g_embx);
    cudaGetSymbolAddress((void**)&wembp, g_Wemb);
    cudaGetSymbolAddress((void**)&gembp, g_gemb);

    // one-time prep
    int prep_total = NG_ * KX2_ + ATT_ * DEC_ + NG_ * EMB_ + T_ * B_ * EMB_;
    k_prep<<<(prep_total + 255) / 256, 256>>>(W_ih, W_hh, W_dec_att, embedding, caption);
    k_init<<<B_, 256>>>(enc, W_init_h, b_init_h, W_init_c, b_init_c);
    // att1[b,p,a] = enc[b,p,:] . W_enc_att[a,:]   (M=12544, N=256, K=512)  fp32
    sgemm128<0><<<dim3(98, 2), 256>>>(enc, W_enc_att, nullptr, att1p, B_ * P_, ATT_, ENC_);
    // gemb[t*B+b][j] = embx . Wemb^T               (M=2816, N=1024, K=256)  fp32
    sgemm128<0><<<dim3(22, 8), 256>>>(embxp, wembp, nullptr, gembp, T_ * B_, NG_, EMB_);

    // recurrence: 3 wide kernels per step
    for (int t = 0; t < T_; t++) {
        k_scores_cell<<<dim3(B_, 7), 256>>>(t, W_full, b_ih, b_hh);
        k_softmax_ctx<<<dim3(B_, 8), 256>>>(t, enc, alphas);
        k_gates<<<dim3(NG_ / 64, SPLITK_), 256>>>();
    }
    k_cell_final<<<B_, 256>>>(b_ih, b_hh);

    // batched logits on tensor cores (tf32): [T*B, DEC] @ W_out^T (+b_out) -> [B, T, V]
    wgemm<1><<<dim3((T_ * B_) / 128, (V_ + 127) / 128), 256>>>(hallp, W_out, b_out, preds,
                                                               T_ * B_, V_, DEC_);
}